// round 6
// baseline (speedup 1.0000x reference)
#include <cuda_runtime.h>
#include <cuda_bf16.h>

#define CG 16
#define HW 4096
#define NG 512            // b*g groups

typedef unsigned long long ull;

// ---------------- scratch (static device allocations are allowed) ----------
__device__ __nv_bfloat16 g_x3[(size_t)NG * CG * HW];   // conv3x3 output (relu'd), 67MB
__device__ float g_ah[NG * CG * 64];
__device__ float g_aw[NG * CG * 64];
__device__ float g_cs[NG * CG * 2];            // max3, V3

// ---------------- warp reduce helpers --------------------------------------
__device__ __forceinline__ float wsum(float v){
  #pragma unroll
  for (int o = 16; o; o >>= 1) v += __shfl_xor_sync(0xffffffffu, v, o);
  return v;
}
__device__ __forceinline__ float wmax(float v){
  #pragma unroll
  for (int o = 16; o; o >>= 1) v = fmaxf(v, __shfl_xor_sync(0xffffffffu, v, o));
  return v;
}
__device__ __forceinline__ float wmin(float v){
  #pragma unroll
  for (int o = 16; o; o >>= 1) v = fminf(v, __shfl_xor_sync(0xffffffffu, v, o));
  return v;
}

// ---------------- packed f32x2 helpers (sm_100+ FFMA2 path) -----------------
__device__ __forceinline__ ull pk2(float lo, float hi){
  ull r;
  asm("mov.b64 %0, {%1, %2};" : "=l"(r) : "f"(lo), "f"(hi));
  return r;
}
__device__ __forceinline__ void fma2(ull& d, ull a, ull b){
  asm("fma.rn.f32x2 %0, %1, %2, %0;" : "+l"(d) : "l"(a), "l"(b));
}
__device__ __forceinline__ float2 upk2(ull v){
  float2 f;
  asm("mov.b64 {%0, %1}, %2;" : "=f"(f.x), "=f"(f.y) : "l"(v));
  return f;
}

// ---------------- cp.async helpers -----------------------------------------
__device__ __forceinline__ void cpa16(float* dst_smem, const float* src, bool valid){
  unsigned sz = valid ? 16u : 0u;
  unsigned d = (unsigned)__cvta_generic_to_shared(dst_smem);
  asm volatile("cp.async.cg.shared.global [%0], [%1], 16, %2;"
               :: "r"(d), "l"(src), "r"(sz) : "memory");
}
__device__ __forceinline__ void cpa_commit(){
  asm volatile("cp.async.commit_group;" ::: "memory");
}
template<int N>
__device__ __forceinline__ void cpa_wait(){
  asm volatile("cp.async.wait_group %0;" :: "n"(N) : "memory");
}

// ---------------- KA smem layout (floats) -----------------------------------
// Tile: data cols at row offsets 0..63 (16B-aligned for cp.async), pads 64..67
// zeroed once (offset 64 = right halo x_64; offset 67 = next row's left x_{-1}).
// A 16-float zero guard precedes buf0 so (ch0,row0) left-halo read at -1 is 0.
#define TILE_RP 68
#define TILE_CP (18 * TILE_RP)     // 1224
#define BUF_FL  (16 * TILE_CP)     // 19584 floats per buffer
#define OFF_B0  16
#define OFF_B1  (16 + BUF_FL)              // 19600
#define OFF_W3D (16 + 2 * BUF_FL)          // 39184 (4608 floats, dup pairs)
#define OFF_RS  (OFF_W3D + 4608)           // 43792 (1024 floats row sums)
#define SM_TOTF (OFF_RS + 1024)            // 44816 floats = 179264 B

__device__ __forceinline__ void issue_strip(float* buf, const float* xc16,
                                            int lane, int r0){
  const int half = lane >> 4, col = (lane & 15) * 4;
  #pragma unroll
  for (int s = 0; s < 9; s++){
    int rr = s * 2 + half;
    int gr = r0 - 1 + rr;
    cpa16(buf + rr * TILE_RP + col, xc16 + gr * 64 + col, (unsigned)gr < 64u);
  }
}

__global__ void __launch_bounds__(512, 1) ka_kernel(
    const float* __restrict__ x,
    const float* __restrict__ w1, const float* __restrict__ b1,
    const float* __restrict__ wh, const float* __restrict__ bh,
    const float* __restrict__ ww, const float* __restrict__ bw,
    const float* __restrict__ w3, const float* __restrict__ b3)
{
  extern __shared__ float sm[];
  float* s_w3d = sm + OFF_W3D;
  float* s_rs  = sm + OFF_RS;      // [16][64] row sums
  // end-phase overlay inside buf0 (safe after last conv)
  float* s_xw = sm + OFF_B0 + 1024;   // [16][64] col sums
  float* s_y  = sm + OFF_B0 + 2048;   // [16][128]
  float* s_W  = sm + OFF_B0 + 4096;   // W1(256) Wh(256) Ww(256)
  float* s_bb = sm + OFF_B0 + 4864;   // b1(16) bh(16) bw(16)

  __shared__ float s_b3[16];
  __shared__ float schmax3[16], schsum3[16];

  const int t = threadIdx.x, warp = t >> 5, lane = t & 31;
  const int g = blockIdx.x;
  const float* xg = x + (size_t)g * CG * HW;
  const float* xch = xg + warp * HW;   // this warp's channel

  // ---- init: guard, pads, weights ----
  if (t < 16) { sm[t] = 0.f; s_b3[t] = b3[t]; schmax3[t] = 0.f; schsum3[t] = 0.f; }
  for (int i = t; i < 576; i += 512) {        // 2 buf * 288 rows
    int b = i >> 8 >> 0;                      // i/288
    b = i / 288;
    int rem = i - b * 288;
    float* row = sm + 16 + b * BUF_FL + rem * TILE_RP;
    row[64] = 0.f; row[65] = 0.f; row[66] = 0.f; row[67] = 0.f;
  }
  for (int i = t; i < 2304; i += 512) {
    float v = w3[i];
    s_w3d[2 * i] = v; s_w3d[2 * i + 1] = v;
  }

  // ---- prefetch strip 0 ----
  issue_strip(sm + OFF_B0 + warp * TILE_CP, xch, lane, 0);
  cpa_commit();

  // ---- strip loop ----
  float4 csum4 = make_float4(0.f, 0.f, 0.f, 0.f);   // per-lane col partial sums
  const int ocp = t >> 6, oc0 = ocp * 2, oc1 = oc0 + 1;
  float m30 = 0.f, m31 = 0.f, s30 = 0.f, s31 = 0.f;
  const ull* w3du = reinterpret_cast<const ull*>(s_w3d);
  const int half = lane >> 4, col4 = (lane & 15) * 4;

  #pragma unroll 1
  for (int s = 0; s < 4; s++) {
    const int r0 = s * 16;
    float* cur = sm + ((s & 1) ? OFF_B1 : OFF_B0);
    if (s < 3) {
      float* nxt = sm + (((s + 1) & 1) ? OFF_B1 : OFF_B0);
      issue_strip(nxt + warp * TILE_CP, xch, lane, r0 + 16);
      cpa_commit();
      cpa_wait<1>();
    } else {
      cpa_wait<0>();
    }
    __syncthreads();                 // strip s visible; prev readers done

    // stats: warp == channel, rows rr=1..16 (each thread 8 steps of 1 float4)
    {
      const float* bch = cur + warp * TILE_CP;
      #pragma unroll
      for (int st = 0; st < 8; st++) {
        int rr = 1 + st * 2 + half;
        float4 v = *reinterpret_cast<const float4*>(bch + rr * TILE_RP + col4);
        csum4.x += v.x; csum4.y += v.y; csum4.z += v.z; csum4.w += v.w;
        float rs = (v.x + v.y) + (v.z + v.w);
        #pragma unroll
        for (int o = 1; o < 16; o <<= 1) rs += __shfl_xor_sync(0xffffffffu, rs, o);
        if ((lane & 15) == 0) s_rs[warp * 64 + r0 + st * 2 + half] = rs;
      }
    }

    // conv: each thread computes 2 tiles of (2 outch x 8 px), packed f32x2
    #pragma unroll 1
    for (int it = 0; it < 2; it++) {
      int ti = (t & 63) + (it << 6);
      int rr = ti >> 3, cb = ti & 7;
      ull Ac0[4], Ac1[4];
      #pragma unroll
      for (int p = 0; p < 4; p++) { Ac0[p] = 0ull; Ac1[p] = 0ull; }
      const float* tb = cur + rr * TILE_RP + cb * 8;
      #pragma unroll 1
      for (int ci = 0; ci < 16; ci++) {
        const float* tcb = tb + ci * TILE_CP;
        const ull* wa = w3du + oc0 * 144 + ci * 9;
        const ull* wb = w3du + oc1 * 144 + ci * 9;
        #pragma unroll
        for (int dr = 0; dr < 3; dr++) {
          const float* base = tcb + dr * TILE_RP;
          const float lft = base[-1];
          const float4 q0 = *reinterpret_cast<const float4*>(base);
          const float4 q1 = *reinterpret_cast<const float4*>(base + 4);
          const float rgt = base[8];
          ull E0 = pk2(q0.x, q0.y), E1 = pk2(q0.z, q0.w);
          ull E2 = pk2(q1.x, q1.y), E3 = pk2(q1.z, q1.w);
          ull A0 = pk2(lft, q0.x);
          ull M0 = pk2(q0.y, q0.z), M1 = pk2(q0.w, q1.x);
          ull M2 = pk2(q1.y, q1.z), M3 = pk2(q1.w, rgt);
          {
            ull u0 = wa[dr * 3], u1 = wa[dr * 3 + 1], u2 = wa[dr * 3 + 2];
            fma2(Ac0[0], u0, A0); fma2(Ac0[0], u1, E0); fma2(Ac0[0], u2, M0);
            fma2(Ac0[1], u0, M0); fma2(Ac0[1], u1, E1); fma2(Ac0[1], u2, M1);
            fma2(Ac0[2], u0, M1); fma2(Ac0[2], u1, E2); fma2(Ac0[2], u2, M2);
            fma2(Ac0[3], u0, M2); fma2(Ac0[3], u1, E3); fma2(Ac0[3], u2, M3);
          }
          {
            ull u0 = wb[dr * 3], u1 = wb[dr * 3 + 1], u2 = wb[dr * 3 + 2];
            fma2(Ac1[0], u0, A0); fma2(Ac1[0], u1, E0); fma2(Ac1[0], u2, M0);
            fma2(Ac1[1], u0, M0); fma2(Ac1[1], u1, E1); fma2(Ac1[1], u2, M1);
            fma2(Ac1[2], u0, M1); fma2(Ac1[2], u1, E2); fma2(Ac1[2], u2, M2);
            fma2(Ac1[3], u0, M2); fma2(Ac1[3], u1, E3); fma2(Ac1[3], u2, M3);
          }
        }
      }
      int grow = r0 + rr;
      float bz0 = s_b3[oc0], bz1 = s_b3[oc1];
      __nv_bfloat162 h0[4], h1[4];
      #pragma unroll
      for (int p = 0; p < 4; p++) {
        float2 f0 = upk2(Ac0[p]);
        float2 f1 = upk2(Ac1[p]);
        float a0 = fmaxf(f0.x + bz0, 0.f), a1 = fmaxf(f0.y + bz0, 0.f);
        float b0v = fmaxf(f1.x + bz1, 0.f), b1v = fmaxf(f1.y + bz1, 0.f);
        m30 = fmaxf(m30, fmaxf(a0, a1)); s30 += a0 + a1;
        m31 = fmaxf(m31, fmaxf(b0v, b1v)); s31 += b0v + b1v;
        h0[p] = __floats2bfloat162_rn(a0, a1);
        h1[p] = __floats2bfloat162_rn(b0v, b1v);
      }
      __nv_bfloat16* o0 = g_x3 + ((size_t)g * CG + oc0) * HW + grow * 64 + cb * 8;
      __nv_bfloat16* o1 = g_x3 + ((size_t)g * CG + oc1) * HW + grow * 64 + cb * 8;
      *reinterpret_cast<uint4*>(o0) = *reinterpret_cast<uint4*>(h0);
      *reinterpret_cast<uint4*>(o1) = *reinterpret_cast<uint4*>(h1);
    }
    __syncthreads();                 // done reading cur before it is refilled
  }

  // ---- end phase: fold col sums, x3 stats, 1x1 convs -----------------------
  csum4.x += __shfl_xor_sync(0xffffffffu, csum4.x, 16);
  csum4.y += __shfl_xor_sync(0xffffffffu, csum4.y, 16);
  csum4.z += __shfl_xor_sync(0xffffffffu, csum4.z, 16);
  csum4.w += __shfl_xor_sync(0xffffffffu, csum4.w, 16);
  if (lane < 16) {
    float* d = s_xw + warp * 64 + lane * 4;
    d[0] = csum4.x; d[1] = csum4.y; d[2] = csum4.z; d[3] = csum4.w;
  }
  if (t < 256) { s_W[t] = w1[t]; s_W[256 + t] = wh[t]; s_W[512 + t] = ww[t]; }
  if (t < 16) { s_bb[t] = b1[t]; s_bb[16 + t] = bh[t]; s_bb[32 + t] = bw[t]; }
  atomicAdd(&schsum3[oc0], s30);
  atomicAdd(&schsum3[oc1], s31);
  atomicMax(reinterpret_cast<int*>(&schmax3[oc0]), __float_as_int(m30)); // relu >= 0
  atomicMax(reinterpret_cast<int*>(&schmax3[oc1]), __float_as_int(m31));
  __syncthreads();

  if (t < 16) {
    float* cs = g_cs + (g * CG + t) * 2;
    cs[0] = schmax3[t];
    cs[1] = schsum3[t] * (1.f / 4096.f);
  }

  // y = relu(W1 @ [xh;xw] + b1)
  if (t < 128) {
    float in[16];
    #pragma unroll
    for (int i = 0; i < 16; i++) {
      float raw = (t < 64) ? s_rs[i * 64 + t] : s_xw[i * 64 + (t - 64)];
      in[i] = raw * (1.f / 64.f);
    }
    #pragma unroll
    for (int o = 0; o < 16; o++) {
      float acc = s_bb[o];
      #pragma unroll
      for (int i = 0; i < 16; i++) acc = fmaf(s_W[o * 16 + i], in[i], acc);
      s_y[o * 128 + t] = fmaxf(acc, 0.f);
    }
  }
  __syncthreads();
  // a_h = sigmoid(Wh @ y_h + bh), a_w = sigmoid(Ww @ y_w + bw) -> gmem
  if (t < 128) {
    const int hf = t >> 6, cc = t & 63;
    const float* Wm = s_W + 256 + hf * 256;
    const float* bm = s_bb + 16 + hf * 16;
    float in[16];
    #pragma unroll
    for (int i = 0; i < 16; i++) in[i] = s_y[i * 128 + t];
    float* gdst = hf ? (g_aw + g * 1024) : (g_ah + g * 1024);
    #pragma unroll
    for (int o = 0; o < 16; o++) {
      float acc = bm[o];
      #pragma unroll
      for (int i = 0; i < 16; i++) acc = fmaf(Wm[o * 16 + i], in[i], acc);
      gdst[o * 64 + cc] = 1.f / (1.f + __expf(-acc));
    }
  }
}

// ---------------------------------------------------------------------------
// KB: unchanged from the 149us configuration (512 thr, L2-resident passes).
__global__ void __launch_bounds__(512) kb_kernel(const float* __restrict__ x,
                                                 const float* __restrict__ gnw,
                                                 const float* __restrict__ gnb,
                                                 float* __restrict__ out)
{
  __shared__ float s_s[4096];
  __shared__ float s_ah[1024], s_aw[1024];
  __shared__ float s_k[16], s_e2[16], s_m3[16], s_w2[16], s_w3[16];
  __shared__ float schsum1[16], schsq1[16], schmax1[16], schmin1[16];
  __shared__ float s_r1[16];
  __shared__ float s_mu, s_rsd, s_smax, s_sinv;

  const int t = threadIdx.x, warp = t >> 5, lane = t & 31;
  const int g = blockIdx.x;
  const float* xg = x + (size_t)g * CG * HW;
  const __nv_bfloat16* x3g = g_x3 + (size_t)g * CG * HW;

  for (int i = t; i < 1024; i += 512) {
    s_ah[i] = g_ah[g * 1024 + i];
    s_aw[i] = g_aw[g * 1024 + i];
  }
  __syncthreads();

  // ---- pass 0: x1 statistics (warp == channel) ----
  {
    const int c = warp;
    const float* xc = xg + c * HW;
    const float* ahc = s_ah + c * 64;
    float aw0 = s_aw[c * 64 + lane * 2];
    float aw1 = s_aw[c * 64 + lane * 2 + 1];
    float sum = 0.f, sq = 0.f, mx = -1e30f, mn = 1e30f;
    #pragma unroll 4
    for (int m = 0; m < 64; m++) {
      float2 xv = *reinterpret_cast<const float2*>(xc + m * 64 + lane * 2);
      float a = ahc[m];
      float v0 = xv.x * a * aw0;
      float v1 = xv.y * a * aw1;
      sum += v0 + v1;
      sq += v0 * v0 + v1 * v1;
      mx = fmaxf(mx, fmaxf(v0, v1));
      mn = fminf(mn, fminf(v0, v1));
    }
    sum = wsum(sum); sq = wsum(sq); mx = wmax(mx); mn = wmin(mn);
    if (lane == 0) {
      schsum1[c] = sum; schsq1[c] = sq; schmax1[c] = mx; schmin1[c] = mn;
    }
  }
  __syncthreads();
  if (t == 0) {
    float a = 0.f, bq = 0.f;
    #pragma unroll
    for (int i = 0; i < 16; i++) { a += schsum1[i]; bq += schsq1[i]; }
    float mu = a * (1.f / 65536.f);
    float var = bq * (1.f / 65536.f) - mu * mu;
    s_mu = mu; s_rsd = rsqrtf(var + 1e-5f);
  }
  __syncthreads();
  if (t < 16) {
    int c = t;
    float k = s_rsd * gnw[c];
    float d = gnb[c] - s_mu * k;
    float mx1 = (k >= 0.f) ? schmax1[c] : schmin1[c];
    float max2 = mx1 * k + d;
    const float* cs = g_cs + (g * CG + c) * 2;
    s_k[c]  = k;
    s_e2[c] = d - max2;
    s_m3[c] = cs[0];                          // max3
    s_w2[c] = cs[1];                          // V3 (÷ Z2 in pass 1)
    s_w3[c] = schsum1[c] * (1.f / 4096.f) * k + d;  // V2 (÷ Z3 in pass 1)
  }
  __syncthreads();

  // ---- pass 1: per-channel Z2, Z3 (warp == channel, L2-hot reads) ----
  {
    const int c = warp;
    float k = s_k[c], e2 = s_e2[c], m3 = s_m3[c];
    const float* xc = xg + c * HW;
    const __nv_bfloat16* x3c = x3g + c * HW;
    const float* ahc = s_ah + c * 64;
    float aw0 = s_aw[c * 64 + lane * 2];
    float aw1 = s_aw[c * 64 + lane * 2 + 1];
    float z2 = 0.f, z3 = 0.f;
    #pragma unroll 4
    for (int m = 0; m < 64; m++) {
      float2 xv = *reinterpret_cast<const float2*>(xc + m * 64 + lane * 2);
      __nv_bfloat162 x3v = *reinterpret_cast<const __nv_bfloat162*>(x3c + m * 64 + lane * 2);
      float a = ahc[m];
      z2 += __expf(fmaf(xv.x * a * aw0, k, e2)) + __expf(fmaf(xv.y * a * aw1, k, e2));
      z3 += __expf(__bfloat162float(x3v.x) - m3) + __expf(__bfloat162float(x3v.y) - m3);
    }
    z2 = wsum(z2); z3 = wsum(z3);
    if (lane == 0) { s_w3[c] = s_w3[c] / z3; s_w2[c] = s_w2[c] / z2; }
  }
  __syncthreads();

  // ---- pass 2: s logits ----
  float lmax = -1e30f;
  #pragma unroll 1
  for (int rep = 0; rep < 8; rep++) {
    int l = t + rep * 512;
    int i = l >> 6, j = l & 63;
    float acc = 0.f;
    #pragma unroll
    for (int c = 0; c < 16; c++) {
      float x1 = xg[c * HW + l] * s_ah[c * 64 + i] * s_aw[c * 64 + j];
      acc += s_w2[c] * __expf(fmaf(x1, s_k[c], s_e2[c]));
      acc += s_w3[c] * __expf(__bfloat162float(x3g[c * HW + l]) - s_m3[c]);
    }
    s_s[l] = acc;
    lmax = fmaxf(lmax, acc);
  }
  lmax = wmax(lmax);
  if (lane == 0) s_r1[warp] = lmax;
  __syncthreads();
  if (t == 0) {
    float m = -1e30f;
    #pragma unroll
    for (int i = 0; i < 16; i++) m = fmaxf(m, s_r1[i]);
    s_smax = m;
  }
  __syncthreads();
  float lsum = 0.f;
  {
    float smax = s_smax;
    #pragma unroll 1
    for (int rep = 0; rep < 8; rep++) {
      int l = t + rep * 512;
      float e = __expf(s_s[l] - smax);
      s_s[l] = e;                           // store exp once
      lsum += e;
    }
  }
  lsum = wsum(lsum);
  if (lane == 0) s_r1[warp] = lsum;
  __syncthreads();
  if (t == 0) {
    float a = 0.f;
    #pragma unroll
    for (int i = 0; i < 16; i++) a += s_r1[i];
    s_sinv = 1.f / a;
  }
  __syncthreads();

  // ---- pass 3: out = x * (e * sinv) ----
  float* og = out + (size_t)g * CG * HW;
  float sinv = s_sinv;
  #pragma unroll 1
  for (int c = 0; c < 16; c++) {
    #pragma unroll
    for (int rep = 0; rep < 4; rep++) {
      int l0 = (t + rep * 512) * 2;
      float2 xv = *reinterpret_cast<const float2*>(xg + c * HW + l0);
      float2 ov;
      ov.x = xv.x * (s_s[l0] * sinv);
      ov.y = xv.y * (s_s[l0 + 1] * sinv);
      *reinterpret_cast<float2*>(og + c * HW + l0) = ov;
    }
  }
}

// ---------------------------------------------------------------------------
extern "C" void kernel_launch(void* const* d_in, const int* in_sizes, int n_in,
                              void* d_out, int out_size)
{
  const float* x   = (const float*)d_in[0];
  const float* w1  = (const float*)d_in[1];
  const float* b1  = (const float*)d_in[2];
  const float* wh  = (const float*)d_in[3];
  const float* bh  = (const float*)d_in[4];
  const float* ww  = (const float*)d_in[5];
  const float* bw  = (const float*)d_in[6];
  const float* w3  = (const float*)d_in[7];
  const float* b3  = (const float*)d_in[8];
  const float* gnw = (const float*)d_in[9];
  const float* gnb = (const float*)d_in[10];

  cudaFuncSetAttribute(ka_kernel, cudaFuncAttributeMaxDynamicSharedMemorySize,
                       SM_TOTF * (int)sizeof(float));
  ka_kernel<<<NG, 512, SM_TOTF * sizeof(float)>>>(x, w1, b1, wh, bh, ww, bw, w3, b3);
  kb_kernel<<<NG, 512>>>(x, gnw, gnb, (float*)d_out);
}

// round 7
// speedup vs baseline: 1.0489x; 1.0489x over previous
#include <cuda_runtime.h>
#include <cuda_bf16.h>

#define CG 16
#define HW 4096
#define NG 512            // b*g groups

typedef unsigned long long ull;

// ---------------- scratch (static device allocations are allowed) ----------
__device__ __nv_bfloat16 g_x3[(size_t)NG * CG * HW];   // conv3x3 output (relu'd), 67MB
__device__ float g_ah[NG * CG * 64];
__device__ float g_aw[NG * CG * 64];
__device__ float g_cs[NG * CG * 2];            // max3, V3

// ---------------- warp reduce helpers --------------------------------------
__device__ __forceinline__ float wsum(float v){
  #pragma unroll
  for (int o = 16; o; o >>= 1) v += __shfl_xor_sync(0xffffffffu, v, o);
  return v;
}
__device__ __forceinline__ float wmax(float v){
  #pragma unroll
  for (int o = 16; o; o >>= 1) v = fmaxf(v, __shfl_xor_sync(0xffffffffu, v, o));
  return v;
}
__device__ __forceinline__ float wmin(float v){
  #pragma unroll
  for (int o = 16; o; o >>= 1) v = fminf(v, __shfl_xor_sync(0xffffffffu, v, o));
  return v;
}

// ---------------- packed f32x2 helpers (sm_100+ FFMA2 path) -----------------
__device__ __forceinline__ ull pk2(float lo, float hi){
  ull r;
  asm("mov.b64 %0, {%1, %2};" : "=l"(r) : "f"(lo), "f"(hi));
  return r;
}
__device__ __forceinline__ void fma2(ull& d, ull a, ull b){
  asm("fma.rn.f32x2 %0, %1, %2, %0;" : "+l"(d) : "l"(a), "l"(b));
}
__device__ __forceinline__ float2 upk2(ull v){
  float2 f;
  asm("mov.b64 {%0, %1}, %2;" : "=f"(f.x), "=f"(f.y) : "l"(v));
  return f;
}

// ---------------- cp.async helpers -----------------------------------------
__device__ __forceinline__ void cpa16(float* dst_smem, const float* src, bool valid){
  unsigned sz = valid ? 16u : 0u;
  unsigned d = (unsigned)__cvta_generic_to_shared(dst_smem);
  asm volatile("cp.async.cg.shared.global [%0], [%1], 16, %2;"
               :: "r"(d), "l"(src), "r"(sz) : "memory");
}
__device__ __forceinline__ void cpa_commit(){
  asm volatile("cp.async.commit_group;" ::: "memory");
}
template<int N>
__device__ __forceinline__ void cpa_wait(){
  asm volatile("cp.async.wait_group %0;" :: "n"(N) : "memory");
}

// ---------------- KA smem layout (floats) -----------------------------------
// 8-row strips (10 rows with halo). Data cols 0..63 (16B aligned for cp.async),
// pads: col 64 = right halo (zero), col 67 = next row's left halo (zero).
// 16-float zero guard before buf0 covers (ch0, row0, col -1).
#define TILE_RP 68
#define TILE_CP (10 * TILE_RP)             // 680
#define BUF_FL  (16 * TILE_CP)             // 10880 floats per buffer
#define OFF_B0  16
#define OFF_B1  (16 + BUF_FL)              // 10896
#define OFF_W3D (16 + 2 * BUF_FL)          // 21776 (4608 floats, dup pairs)
#define OFF_RS  (OFF_W3D + 4608)           // 26384 (1024 floats row sums)
#define SM_TOTF (OFF_RS + 1024)            // 27408 floats = 109632 B

// Each warp loads its channel's 10 rows x 16 16B-chunks = 160 chunks, 5/lane.
__device__ __forceinline__ void issue_strip(float* buf, const float* xc16,
                                            int lane, int r0){
  #pragma unroll
  for (int s = 0; s < 5; s++){
    int chunk = lane + s * 32;
    int rr = chunk >> 4;                   // 0..9
    int col = (chunk & 15) * 4;
    int gr = r0 - 1 + rr;
    cpa16(buf + rr * TILE_RP + col, xc16 + gr * 64 + col, (unsigned)gr < 64u);
  }
}

__global__ void __launch_bounds__(512, 2) ka_kernel(
    const float* __restrict__ x,
    const float* __restrict__ w1, const float* __restrict__ b1,
    const float* __restrict__ wh, const float* __restrict__ bh,
    const float* __restrict__ ww, const float* __restrict__ bw,
    const float* __restrict__ w3, const float* __restrict__ b3)
{
  extern __shared__ float sm[];
  float* s_w3d = sm + OFF_W3D;
  float* s_rs  = sm + OFF_RS;         // [16][64] row sums
  // end-phase overlay inside buf0 (safe after last conv)
  float* s_xw = sm + OFF_B0 + 1024;   // [16][64] col sums
  float* s_y  = sm + OFF_B0 + 2048;   // [16][128]
  float* s_W  = sm + OFF_B0 + 4096;   // W1(256) Wh(256) Ww(256)
  float* s_bb = sm + OFF_B0 + 4864;   // b1(16) bh(16) bw(16)

  __shared__ float s_b3[16];
  __shared__ float schmax3[16], schsum3[16];

  const int t = threadIdx.x, warp = t >> 5, lane = t & 31;
  const int g = blockIdx.x;
  const float* xg = x + (size_t)g * CG * HW;
  const float* xch = xg + warp * HW;   // this warp's channel

  // ---- init: guard, pads, weights ----
  if (t < 16) { sm[t] = 0.f; s_b3[t] = b3[t]; schmax3[t] = 0.f; schsum3[t] = 0.f; }
  for (int i = t; i < 320; i += 512) {        // 2 buf * 160 rows
    int b = i >> 7 >> 0;
    b = i / 160;
    int rem = i - b * 160;
    float* row = sm + 16 + b * BUF_FL + rem * TILE_RP;
    row[64] = 0.f; row[65] = 0.f; row[66] = 0.f; row[67] = 0.f;
  }
  for (int i = t; i < 2304; i += 512) {
    float v = w3[i];
    s_w3d[2 * i] = v; s_w3d[2 * i + 1] = v;
  }

  // ---- prefetch strip 0 ----
  issue_strip(sm + OFF_B0 + warp * TILE_CP, xch, lane, 0);
  cpa_commit();

  // ---- strip loop: 8 strips of 8 rows ----
  float4 csum4 = make_float4(0.f, 0.f, 0.f, 0.f);   // per-lane col partial sums
  const int ocp = t >> 6, oc0 = ocp * 2, oc1 = oc0 + 1;
  const int ti = t & 63, rr = ti >> 3, cb = ti & 7;
  float m30 = 0.f, m31 = 0.f, s30 = 0.f, s31 = 0.f;
  const ull* w3du = reinterpret_cast<const ull*>(s_w3d);
  const int half = lane >> 4, col4 = (lane & 15) * 4;

  #pragma unroll 1
  for (int s = 0; s < 8; s++) {
    const int r0 = s * 8;
    float* cur = sm + ((s & 1) ? OFF_B1 : OFF_B0);
    if (s < 7) {
      float* nxt = sm + (((s + 1) & 1) ? OFF_B1 : OFF_B0);
      issue_strip(nxt + warp * TILE_CP, xch, lane, r0 + 8);
      cpa_commit();
      cpa_wait<1>();
    } else {
      cpa_wait<0>();
    }
    __syncthreads();                 // strip s visible; prev readers done

    // stats: warp == channel, data rows b=1..8 (4 float4 steps per thread)
    {
      const float* bch = cur + warp * TILE_CP;
      #pragma unroll
      for (int st = 0; st < 4; st++) {
        int b = 1 + st * 2 + half;
        float4 v = *reinterpret_cast<const float4*>(bch + b * TILE_RP + col4);
        csum4.x += v.x; csum4.y += v.y; csum4.z += v.z; csum4.w += v.w;
        float rs = (v.x + v.y) + (v.z + v.w);
        #pragma unroll
        for (int o = 1; o < 16; o <<= 1) rs += __shfl_xor_sync(0xffffffffu, rs, o);
        if ((lane & 15) == 0) s_rs[warp * 64 + r0 + st * 2 + half] = rs;
      }
    }

    // conv: one (2 outch x 8 px) tile per thread, packed f32x2
    {
      ull Ac0[4], Ac1[4];
      #pragma unroll
      for (int p = 0; p < 4; p++) { Ac0[p] = 0ull; Ac1[p] = 0ull; }
      const float* tb = cur + rr * TILE_RP + cb * 8;
      #pragma unroll 1
      for (int ci = 0; ci < 16; ci++) {
        const float* tcb = tb + ci * TILE_CP;
        const ull* wa = w3du + oc0 * 144 + ci * 9;
        const ull* wb = w3du + oc1 * 144 + ci * 9;
        #pragma unroll
        for (int dr = 0; dr < 3; dr++) {
          const float* base = tcb + dr * TILE_RP;
          const float lft = base[-1];
          const float4 q0 = *reinterpret_cast<const float4*>(base);
          const float4 q1 = *reinterpret_cast<const float4*>(base + 4);
          const float rgt = base[8];
          ull E0 = pk2(q0.x, q0.y), E1 = pk2(q0.z, q0.w);
          ull E2 = pk2(q1.x, q1.y), E3 = pk2(q1.z, q1.w);
          ull A0 = pk2(lft, q0.x);
          ull M0 = pk2(q0.y, q0.z), M1 = pk2(q0.w, q1.x);
          ull M2 = pk2(q1.y, q1.z), M3 = pk2(q1.w, rgt);
          {
            ull u0 = wa[dr * 3], u1 = wa[dr * 3 + 1], u2 = wa[dr * 3 + 2];
            fma2(Ac0[0], u0, A0); fma2(Ac0[0], u1, E0); fma2(Ac0[0], u2, M0);
            fma2(Ac0[1], u0, M0); fma2(Ac0[1], u1, E1); fma2(Ac0[1], u2, M1);
            fma2(Ac0[2], u0, M1); fma2(Ac0[2], u1, E2); fma2(Ac0[2], u2, M2);
            fma2(Ac0[3], u0, M2); fma2(Ac0[3], u1, E3); fma2(Ac0[3], u2, M3);
          }
          {
            ull u0 = wb[dr * 3], u1 = wb[dr * 3 + 1], u2 = wb[dr * 3 + 2];
            fma2(Ac1[0], u0, A0); fma2(Ac1[0], u1, E0); fma2(Ac1[0], u2, M0);
            fma2(Ac1[1], u0, M0); fma2(Ac1[1], u1, E1); fma2(Ac1[1], u2, M1);
            fma2(Ac1[2], u0, M1); fma2(Ac1[2], u1, E2); fma2(Ac1[2], u2, M2);
            fma2(Ac1[3], u0, M2); fma2(Ac1[3], u1, E3); fma2(Ac1[3], u2, M3);
          }
        }
      }
      int grow = r0 + rr;
      float bz0 = s_b3[oc0], bz1 = s_b3[oc1];
      __nv_bfloat162 h0[4], h1[4];
      #pragma unroll
      for (int p = 0; p < 4; p++) {
        float2 f0 = upk2(Ac0[p]);
        float2 f1 = upk2(Ac1[p]);
        float a0 = fmaxf(f0.x + bz0, 0.f), a1 = fmaxf(f0.y + bz0, 0.f);
        float b0v = fmaxf(f1.x + bz1, 0.f), b1v = fmaxf(f1.y + bz1, 0.f);
        m30 = fmaxf(m30, fmaxf(a0, a1)); s30 += a0 + a1;
        m31 = fmaxf(m31, fmaxf(b0v, b1v)); s31 += b0v + b1v;
        h0[p] = __floats2bfloat162_rn(a0, a1);
        h1[p] = __floats2bfloat162_rn(b0v, b1v);
      }
      __nv_bfloat16* o0 = g_x3 + ((size_t)g * CG + oc0) * HW + grow * 64 + cb * 8;
      __nv_bfloat16* o1 = g_x3 + ((size_t)g * CG + oc1) * HW + grow * 64 + cb * 8;
      *reinterpret_cast<uint4*>(o0) = *reinterpret_cast<uint4*>(h0);
      *reinterpret_cast<uint4*>(o1) = *reinterpret_cast<uint4*>(h1);
    }
    __syncthreads();                 // done reading cur before it is refilled
  }

  // ---- end phase: fold col sums, x3 stats, 1x1 convs -----------------------
  csum4.x += __shfl_xor_sync(0xffffffffu, csum4.x, 16);
  csum4.y += __shfl_xor_sync(0xffffffffu, csum4.y, 16);
  csum4.z += __shfl_xor_sync(0xffffffffu, csum4.z, 16);
  csum4.w += __shfl_xor_sync(0xffffffffu, csum4.w, 16);
  if (lane < 16) {
    float* d = s_xw + warp * 64 + lane * 4;
    d[0] = csum4.x; d[1] = csum4.y; d[2] = csum4.z; d[3] = csum4.w;
  }
  if (t < 256) { s_W[t] = w1[t]; s_W[256 + t] = wh[t]; s_W[512 + t] = ww[t]; }
  if (t < 16) { s_bb[t] = b1[t]; s_bb[16 + t] = bh[t]; s_bb[32 + t] = bw[t]; }
  atomicAdd(&schsum3[oc0], s30);
  atomicAdd(&schsum3[oc1], s31);
  atomicMax(reinterpret_cast<int*>(&schmax3[oc0]), __float_as_int(m30)); // relu >= 0
  atomicMax(reinterpret_cast<int*>(&schmax3[oc1]), __float_as_int(m31));
  __syncthreads();

  if (t < 16) {
    float* cs = g_cs + (g * CG + t) * 2;
    cs[0] = schmax3[t];
    cs[1] = schsum3[t] * (1.f / 4096.f);
  }

  // y = relu(W1 @ [xh;xw] + b1)
  if (t < 128) {
    float in[16];
    #pragma unroll
    for (int i = 0; i < 16; i++) {
      float raw = (t < 64) ? s_rs[i * 64 + t] : s_xw[i * 64 + (t - 64)];
      in[i] = raw * (1.f / 64.f);
    }
    #pragma unroll
    for (int o = 0; o < 16; o++) {
      float acc = s_bb[o];
      #pragma unroll
      for (int i = 0; i < 16; i++) acc = fmaf(s_W[o * 16 + i], in[i], acc);
      s_y[o * 128 + t] = fmaxf(acc, 0.f);
    }
  }
  __syncthreads();
  // a_h = sigmoid(Wh @ y_h + bh), a_w = sigmoid(Ww @ y_w + bw) -> gmem
  if (t < 128) {
    const int hf = t >> 6, cc = t & 63;
    const float* Wm = s_W + 256 + hf * 256;
    const float* bm = s_bb + 16 + hf * 16;
    float in[16];
    #pragma unroll
    for (int i = 0; i < 16; i++) in[i] = s_y[i * 128 + t];
    float* gdst = hf ? (g_aw + g * 1024) : (g_ah + g * 1024);
    #pragma unroll
    for (int o = 0; o < 16; o++) {
      float acc = bm[o];
      #pragma unroll
      for (int i = 0; i < 16; i++) acc = fmaf(Wm[o * 16 + i], in[i], acc);
      gdst[o * 64 + cc] = 1.f / (1.f + __expf(-acc));
    }
  }
}

// ---------------------------------------------------------------------------
// KB: unchanged from the 149us configuration (512 thr, L2-resident passes).
__global__ void __launch_bounds__(512) kb_kernel(const float* __restrict__ x,
                                                 const float* __restrict__ gnw,
                                                 const float* __restrict__ gnb,
                                                 float* __restrict__ out)
{
  __shared__ float s_s[4096];
  __shared__ float s_ah[1024], s_aw[1024];
  __shared__ float s_k[16], s_e2[16], s_m3[16], s_w2[16], s_w3[16];
  __shared__ float schsum1[16], schsq1[16], schmax1[16], schmin1[16];
  __shared__ float s_r1[16];
  __shared__ float s_mu, s_rsd, s_smax, s_sinv;

  const int t = threadIdx.x, warp = t >> 5, lane = t & 31;
  const int g = blockIdx.x;
  const float* xg = x + (size_t)g * CG * HW;
  const __nv_bfloat16* x3g = g_x3 + (size_t)g * CG * HW;

  for (int i = t; i < 1024; i += 512) {
    s_ah[i] = g_ah[g * 1024 + i];
    s_aw[i] = g_aw[g * 1024 + i];
  }
  __syncthreads();

  // ---- pass 0: x1 statistics (warp == channel) ----
  {
    const int c = warp;
    const float* xc = xg + c * HW;
    const float* ahc = s_ah + c * 64;
    float aw0 = s_aw[c * 64 + lane * 2];
    float aw1 = s_aw[c * 64 + lane * 2 + 1];
    float sum = 0.f, sq = 0.f, mx = -1e30f, mn = 1e30f;
    #pragma unroll 4
    for (int m = 0; m < 64; m++) {
      float2 xv = *reinterpret_cast<const float2*>(xc + m * 64 + lane * 2);
      float a = ahc[m];
      float v0 = xv.x * a * aw0;
      float v1 = xv.y * a * aw1;
      sum += v0 + v1;
      sq += v0 * v0 + v1 * v1;
      mx = fmaxf(mx, fmaxf(v0, v1));
      mn = fminf(mn, fminf(v0, v1));
    }
    sum = wsum(sum); sq = wsum(sq); mx = wmax(mx); mn = wmin(mn);
    if (lane == 0) {
      schsum1[c] = sum; schsq1[c] = sq; schmax1[c] = mx; schmin1[c] = mn;
    }
  }
  __syncthreads();
  if (t == 0) {
    float a = 0.f, bq = 0.f;
    #pragma unroll
    for (int i = 0; i < 16; i++) { a += schsum1[i]; bq += schsq1[i]; }
    float mu = a * (1.f / 65536.f);
    float var = bq * (1.f / 65536.f) - mu * mu;
    s_mu = mu; s_rsd = rsqrtf(var + 1e-5f);
  }
  __syncthreads();
  if (t < 16) {
    int c = t;
    float k = s_rsd * gnw[c];
    float d = gnb[c] - s_mu * k;
    float mx1 = (k >= 0.f) ? schmax1[c] : schmin1[c];
    float max2 = mx1 * k + d;
    const float* cs = g_cs + (g * CG + c) * 2;
    s_k[c]  = k;
    s_e2[c] = d - max2;
    s_m3[c] = cs[0];                          // max3
    s_w2[c] = cs[1];                          // V3 (÷ Z2 in pass 1)
    s_w3[c] = schsum1[c] * (1.f / 4096.f) * k + d;  // V2 (÷ Z3 in pass 1)
  }
  __syncthreads();

  // ---- pass 1: per-channel Z2, Z3 (warp == channel, L2-hot reads) ----
  {
    const int c = warp;
    float k = s_k[c], e2 = s_e2[c], m3 = s_m3[c];
    const float* xc = xg + c * HW;
    const __nv_bfloat16* x3c = x3g + c * HW;
    const float* ahc = s_ah + c * 64;
    float aw0 = s_aw[c * 64 + lane * 2];
    float aw1 = s_aw[c * 64 + lane * 2 + 1];
    float z2 = 0.f, z3 = 0.f;
    #pragma unroll 4
    for (int m = 0; m < 64; m++) {
      float2 xv = *reinterpret_cast<const float2*>(xc + m * 64 + lane * 2);
      __nv_bfloat162 x3v = *reinterpret_cast<const __nv_bfloat162*>(x3c + m * 64 + lane * 2);
      float a = ahc[m];
      z2 += __expf(fmaf(xv.x * a * aw0, k, e2)) + __expf(fmaf(xv.y * a * aw1, k, e2));
      z3 += __expf(__bfloat162float(x3v.x) - m3) + __expf(__bfloat162float(x3v.y) - m3);
    }
    z2 = wsum(z2); z3 = wsum(z3);
    if (lane == 0) { s_w3[c] = s_w3[c] / z3; s_w2[c] = s_w2[c] / z2; }
  }
  __syncthreads();

  // ---- pass 2: s logits ----
  float lmax = -1e30f;
  #pragma unroll 1
  for (int rep = 0; rep < 8; rep++) {
    int l = t + rep * 512;
    int i = l >> 6, j = l & 63;
    float acc = 0.f;
    #pragma unroll
    for (int c = 0; c < 16; c++) {
      float x1 = xg[c * HW + l] * s_ah[c * 64 + i] * s_aw[c * 64 + j];
      acc += s_w2[c] * __expf(fmaf(x1, s_k[c], s_e2[c]));
      acc += s_w3[c] * __expf(__bfloat162float(x3g[c * HW + l]) - s_m3[c]);
    }
    s_s[l] = acc;
    lmax = fmaxf(lmax, acc);
  }
  lmax = wmax(lmax);
  if (lane == 0) s_r1[warp] = lmax;
  __syncthreads();
  if (t == 0) {
    float m = -1e30f;
    #pragma unroll
    for (int i = 0; i < 16; i++) m = fmaxf(m, s_r1[i]);
    s_smax = m;
  }
  __syncthreads();
  float lsum = 0.f;
  {
    float smax = s_smax;
    #pragma unroll 1
    for (int rep = 0; rep < 8; rep++) {
      int l = t + rep * 512;
      float e = __expf(s_s[l] - smax);
      s_s[l] = e;                           // store exp once
      lsum += e;
    }
  }
  lsum = wsum(lsum);
  if (lane == 0) s_r1[warp] = lsum;
  __syncthreads();
  if (t == 0) {
    float a = 0.f;
    #pragma unroll
    for (int i = 0; i < 16; i++) a += s_r1[i];
    s_sinv = 1.f / a;
  }
  __syncthreads();

  // ---- pass 3: out = x * (e * sinv) ----
  float* og = out + (size_t)g * CG * HW;
  float sinv = s_sinv;
  #pragma unroll 1
  for (int c = 0; c < 16; c++) {
    #pragma unroll
    for (int rep = 0; rep < 4; rep++) {
      int l0 = (t + rep * 512) * 2;
      float2 xv = *reinterpret_cast<const float2*>(xg + c * HW + l0);
      float2 ov;
      ov.x = xv.x * (s_s[l0] * sinv);
      ov.y = xv.y * (s_s[l0 + 1] * sinv);
      *reinterpret_cast<float2*>(og + c * HW + l0) = ov;
    }
  }
}

// ---------------------------------------------------------------------------
extern "C" void kernel_launch(void* const* d_in, const int* in_sizes, int n_in,
                              void* d_out, int out_size)
{
  const float* x   = (const float*)d_in[0];
  const float* w1  = (const float*)d_in[1];
  const float* b1  = (const float*)d_in[2];
  const float* wh  = (const float*)d_in[3];
  const float* bh  = (const float*)d_in[4];
  const float* ww  = (const float*)d_in[5];
  const float* bw  = (const float*)d_in[6];
  const float* w3  = (const float*)d_in[7];
  const float* b3  = (const float*)d_in[8];
  const float* gnw = (const float*)d_in[9];
  const float* gnb = (const float*)d_in[10];

  cudaFuncSetAttribute(ka_kernel, cudaFuncAttributeMaxDynamicSharedMemorySize,
                       SM_TOTF * (int)sizeof(float));
  ka_kernel<<<NG, 512, SM_TOTF * sizeof(float)>>>(x, w1, b1, wh, bh, ww, bw, w3, b3);
  kb_kernel<<<NG, 512>>>(x, gnw, gnb, (float*)d_out);
}

// round 8
// speedup vs baseline: 1.1433x; 1.0901x over previous
#include <cuda_runtime.h>
#include <cuda_bf16.h>

#define CG 16
#define HW 4096
#define NG 512            // b*g groups

typedef unsigned long long ull;

// ---------------- scratch (static device allocations are allowed) ----------
__device__ __nv_bfloat16 g_x3[(size_t)NG * CG * HW];   // conv3x3 output (relu'd), 67MB
__device__ float g_ah[NG * CG * 64];
__device__ float g_aw[NG * CG * 64];
__device__ float g_cs[NG * CG * 2];            // max3, V3

// ---------------- warp reduce helpers --------------------------------------
__device__ __forceinline__ float wsum(float v){
  #pragma unroll
  for (int o = 16; o; o >>= 1) v += __shfl_xor_sync(0xffffffffu, v, o);
  return v;
}
__device__ __forceinline__ float wmax(float v){
  #pragma unroll
  for (int o = 16; o; o >>= 1) v = fmaxf(v, __shfl_xor_sync(0xffffffffu, v, o));
  return v;
}
__device__ __forceinline__ float wmin(float v){
  #pragma unroll
  for (int o = 16; o; o >>= 1) v = fminf(v, __shfl_xor_sync(0xffffffffu, v, o));
  return v;
}

// ---------------- packed f32x2 helpers (sm_100+ FFMA2 path) -----------------
__device__ __forceinline__ ull pk2(float lo, float hi){
  ull r;
  asm("mov.b64 %0, {%1, %2};" : "=l"(r) : "f"(lo), "f"(hi));
  return r;
}
__device__ __forceinline__ void fma2(ull& d, ull a, ull b){
  asm("fma.rn.f32x2 %0, %1, %2, %0;" : "+l"(d) : "l"(a), "l"(b));
}
__device__ __forceinline__ float2 upk2(ull v){
  float2 f;
  asm("mov.b64 {%0, %1}, %2;" : "=f"(f.x), "=f"(f.y) : "l"(v));
  return f;
}

// ---------------- cp.async helpers -----------------------------------------
__device__ __forceinline__ void cpa16(float* dst_smem, const float* src, bool valid){
  unsigned sz = valid ? 16u : 0u;
  unsigned d = (unsigned)__cvta_generic_to_shared(dst_smem);
  asm volatile("cp.async.cg.shared.global [%0], [%1], 16, %2;"
               :: "r"(d), "l"(src), "r"(sz) : "memory");
}
__device__ __forceinline__ void cpa_commit(){
  asm volatile("cp.async.commit_group;" ::: "memory");
}
template<int N>
__device__ __forceinline__ void cpa_wait(){
  asm volatile("cp.async.wait_group %0;" :: "n"(N) : "memory");
}

// ---------------- KA smem layout (floats) -----------------------------------
// 16-row strips (18 rows with top/bottom halo). Data cols 0..63 (16B aligned),
// pads 64..67 zeroed once: col 64 = right halo; col 67 = next row's left halo.
// 16-float zero guard before the tile covers (ch0, row0, col -1).
#define TILE_RP 68
#define TILE_CP (18 * TILE_RP)             // 1224
#define OFF_T   16
#define OFF_W3D (16 + 16 * TILE_CP)        // 19600 (4608 floats, dup pairs)
#define OFF_RS  (OFF_W3D + 4608)           // 24208 (1024 floats row sums)
#define SM_TOTF (OFF_RS + 1024)            // 25232 floats = 100928 B (2 CTA/SM)

// Each warp loads its channel's 18 rows x 16 16B-chunks = 288 chunks, 9/lane.
__device__ __forceinline__ void issue_strip(float* buf, const float* xc16,
                                            int lane, int r0){
  #pragma unroll
  for (int s = 0; s < 9; s++){
    int chunk = lane + s * 32;
    int rr = chunk >> 4;                   // 0..17
    int col = (chunk & 15) * 4;
    int gr = r0 - 1 + rr;
    cpa16(buf + rr * TILE_RP + col, xc16 + gr * 64 + col, (unsigned)gr < 64u);
  }
}

__global__ void __launch_bounds__(512, 2) ka_kernel(
    const float* __restrict__ x,
    const float* __restrict__ w1, const float* __restrict__ b1,
    const float* __restrict__ wh, const float* __restrict__ bh,
    const float* __restrict__ ww, const float* __restrict__ bw,
    const float* __restrict__ w3, const float* __restrict__ b3)
{
  extern __shared__ float sm[];
  float* tile  = sm + OFF_T;
  float* s_w3d = sm + OFF_W3D;
  float* s_rs  = sm + OFF_RS;         // [16][64] row sums
  // end-phase overlay inside tile (safe after last conv sync)
  float* s_xw = sm + OFF_T + 1024;    // [16][64] col sums
  float* s_y  = sm + OFF_T + 2048;    // [16][128]
  float* s_W  = sm + OFF_T + 4096;    // W1(256) Wh(256) Ww(256)
  float* s_bb = sm + OFF_T + 4864;    // b1(16) bh(16) bw(16)

  __shared__ float s_b3[16];
  __shared__ float schmax3[16], schsum3[16];

  const int t = threadIdx.x, warp = t >> 5, lane = t & 31;
  const int g = blockIdx.x;
  const float* xg = x + (size_t)g * CG * HW;
  const float* xch = xg + warp * HW;   // this warp's channel

  // ---- init: guard, pads, weights ----
  if (t < 16) { sm[t] = 0.f; s_b3[t] = b3[t]; schmax3[t] = 0.f; schsum3[t] = 0.f; }
  if (t < 288) {                              // 16 ch * 18 rows
    float* row = tile + t * TILE_RP;
    row[64] = 0.f; row[65] = 0.f; row[66] = 0.f; row[67] = 0.f;
  }
  for (int i = t; i < 2304; i += 512) {
    float v = w3[i];
    s_w3d[2 * i] = v; s_w3d[2 * i + 1] = v;
  }

  // ---- strip loop: 4 strips of 16 rows (single buffer, 2 CTA/SM overlap) ---
  float4 csum4 = make_float4(0.f, 0.f, 0.f, 0.f);   // per-lane col partial sums
  const int ocp = t >> 6, oc0 = ocp * 2, oc1 = oc0 + 1;
  const int ti = t & 63, rr = ti >> 2, cb = ti & 3; // row 0..15, 16-px colblk 0..3
  float m30 = 0.f, m31 = 0.f, s30 = 0.f, s31 = 0.f;
  const ull* w3du = reinterpret_cast<const ull*>(s_w3d);
  const int half = lane >> 4, col4 = (lane & 15) * 4;

  #pragma unroll 1
  for (int s = 0; s < 4; s++) {
    const int r0 = s * 16;
    issue_strip(tile + warp * TILE_CP, xch, lane, r0);
    cpa_commit();
    cpa_wait<0>();
    __syncthreads();                 // strip visible to all

    // stats: warp == channel, data rows 1..16 (8 float4 steps per thread)
    {
      const float* bch = tile + warp * TILE_CP;
      #pragma unroll
      for (int st = 0; st < 8; st++) {
        int b = 1 + st * 2 + half;
        float4 v = *reinterpret_cast<const float4*>(bch + b * TILE_RP + col4);
        csum4.x += v.x; csum4.y += v.y; csum4.z += v.z; csum4.w += v.w;
        float rs = (v.x + v.y) + (v.z + v.w);
        #pragma unroll
        for (int o = 1; o < 16; o <<= 1) rs += __shfl_xor_sync(0xffffffffu, rs, o);
        if ((lane & 15) == 0) s_rs[warp * 64 + r0 + st * 2 + half] = rs;
      }
    }

    // conv: one (2 outch x 16 px) tile per thread, packed f32x2
    {
      ull Ac0[8], Ac1[8];
      #pragma unroll
      for (int p = 0; p < 8; p++) { Ac0[p] = 0ull; Ac1[p] = 0ull; }
      const float* tb = tile + rr * TILE_RP + cb * 16;
      #pragma unroll 1
      for (int ci = 0; ci < 16; ci++) {
        const float* tcb = tb + ci * TILE_CP;
        const ull* wa = w3du + oc0 * 144 + ci * 9;
        const ull* wb = w3du + oc1 * 144 + ci * 9;
        #pragma unroll
        for (int dr = 0; dr < 3; dr++) {
          const float* base = tcb + dr * TILE_RP;
          const float lft = base[-1];
          const float4 q0 = *reinterpret_cast<const float4*>(base);
          const float4 q1 = *reinterpret_cast<const float4*>(base + 4);
          const float4 q2 = *reinterpret_cast<const float4*>(base + 8);
          const float4 q3 = *reinterpret_cast<const float4*>(base + 12);
          const float rgt = base[16];
          // even pairs (free: aligned reg pairs from LDS.128)
          ull E0 = pk2(q0.x, q0.y), E1 = pk2(q0.z, q0.w);
          ull E2 = pk2(q1.x, q1.y), E3 = pk2(q1.z, q1.w);
          ull E4 = pk2(q2.x, q2.y), E5 = pk2(q2.z, q2.w);
          ull E6 = pk2(q3.x, q3.y), E7 = pk2(q3.z, q3.w);
          // odd pairs: O_p = (x[2p-1], x[2p]); O8 tail = (x15, rgt)
          ull O0 = pk2(lft,  q0.x), O1 = pk2(q0.y, q0.z);
          ull O2 = pk2(q0.w, q1.x), O3 = pk2(q1.y, q1.z);
          ull O4 = pk2(q1.w, q2.x), O5 = pk2(q2.y, q2.z);
          ull O6 = pk2(q2.w, q3.x), O7 = pk2(q3.y, q3.z);
          ull O8 = pk2(q3.w, rgt);
          {
            ull u0 = wa[dr * 3], u1 = wa[dr * 3 + 1], u2 = wa[dr * 3 + 2];
            fma2(Ac0[0], u0, O0); fma2(Ac0[0], u1, E0); fma2(Ac0[0], u2, O1);
            fma2(Ac0[1], u0, O1); fma2(Ac0[1], u1, E1); fma2(Ac0[1], u2, O2);
            fma2(Ac0[2], u0, O2); fma2(Ac0[2], u1, E2); fma2(Ac0[2], u2, O3);
            fma2(Ac0[3], u0, O3); fma2(Ac0[3], u1, E3); fma2(Ac0[3], u2, O4);
            fma2(Ac0[4], u0, O4); fma2(Ac0[4], u1, E4); fma2(Ac0[4], u2, O5);
            fma2(Ac0[5], u0, O5); fma2(Ac0[5], u1, E5); fma2(Ac0[5], u2, O6);
            fma2(Ac0[6], u0, O6); fma2(Ac0[6], u1, E6); fma2(Ac0[6], u2, O7);
            fma2(Ac0[7], u0, O7); fma2(Ac0[7], u1, E7); fma2(Ac0[7], u2, O8);
          }
          {
            ull u0 = wb[dr * 3], u1 = wb[dr * 3 + 1], u2 = wb[dr * 3 + 2];
            fma2(Ac1[0], u0, O0); fma2(Ac1[0], u1, E0); fma2(Ac1[0], u2, O1);
            fma2(Ac1[1], u0, O1); fma2(Ac1[1], u1, E1); fma2(Ac1[1], u2, O2);
            fma2(Ac1[2], u0, O2); fma2(Ac1[2], u1, E2); fma2(Ac1[2], u2, O3);
            fma2(Ac1[3], u0, O3); fma2(Ac1[3], u1, E3); fma2(Ac1[3], u2, O4);
            fma2(Ac1[4], u0, O4); fma2(Ac1[4], u1, E4); fma2(Ac1[4], u2, O5);
            fma2(Ac1[5], u0, O5); fma2(Ac1[5], u1, E5); fma2(Ac1[5], u2, O6);
            fma2(Ac1[6], u0, O6); fma2(Ac1[6], u1, E6); fma2(Ac1[6], u2, O7);
            fma2(Ac1[7], u0, O7); fma2(Ac1[7], u1, E7); fma2(Ac1[7], u2, O8);
          }
        }
      }
      int grow = r0 + rr;
      float bz0 = s_b3[oc0], bz1 = s_b3[oc1];
      __nv_bfloat162 h0[8], h1[8];
      #pragma unroll
      for (int p = 0; p < 8; p++) {
        float2 f0 = upk2(Ac0[p]);
        float2 f1 = upk2(Ac1[p]);
        float a0 = fmaxf(f0.x + bz0, 0.f), a1 = fmaxf(f0.y + bz0, 0.f);
        float b0v = fmaxf(f1.x + bz1, 0.f), b1v = fmaxf(f1.y + bz1, 0.f);
        m30 = fmaxf(m30, fmaxf(a0, a1)); s30 += a0 + a1;
        m31 = fmaxf(m31, fmaxf(b0v, b1v)); s31 += b0v + b1v;
        h0[p] = __floats2bfloat162_rn(a0, a1);
        h1[p] = __floats2bfloat162_rn(b0v, b1v);
      }
      __nv_bfloat16* o0 = g_x3 + ((size_t)g * CG + oc0) * HW + grow * 64 + cb * 16;
      __nv_bfloat16* o1 = g_x3 + ((size_t)g * CG + oc1) * HW + grow * 64 + cb * 16;
      *reinterpret_cast<uint4*>(o0)     = *reinterpret_cast<uint4*>(h0);
      *reinterpret_cast<uint4*>(o0 + 8) = *reinterpret_cast<uint4*>(h0 + 4);
      *reinterpret_cast<uint4*>(o1)     = *reinterpret_cast<uint4*>(h1);
      *reinterpret_cast<uint4*>(o1 + 8) = *reinterpret_cast<uint4*>(h1 + 4);
    }
    __syncthreads();                 // done reading tile before refill
  }

  // ---- end phase: fold col sums, x3 stats, 1x1 convs -----------------------
  csum4.x += __shfl_xor_sync(0xffffffffu, csum4.x, 16);
  csum4.y += __shfl_xor_sync(0xffffffffu, csum4.y, 16);
  csum4.z += __shfl_xor_sync(0xffffffffu, csum4.z, 16);
  csum4.w += __shfl_xor_sync(0xffffffffu, csum4.w, 16);
  if (lane < 16) {
    float* d = s_xw + warp * 64 + lane * 4;
    d[0] = csum4.x; d[1] = csum4.y; d[2] = csum4.z; d[3] = csum4.w;
  }
  if (t < 256) { s_W[t] = w1[t]; s_W[256 + t] = wh[t]; s_W[512 + t] = ww[t]; }
  if (t < 16) { s_bb[t] = b1[t]; s_bb[16 + t] = bh[t]; s_bb[32 + t] = bw[t]; }
  atomicAdd(&schsum3[oc0], s30);
  atomicAdd(&schsum3[oc1], s31);
  atomicMax(reinterpret_cast<int*>(&schmax3[oc0]), __float_as_int(m30)); // relu >= 0
  atomicMax(reinterpret_cast<int*>(&schmax3[oc1]), __float_as_int(m31));
  __syncthreads();

  if (t < 16) {
    float* cs = g_cs + (g * CG + t) * 2;
    cs[0] = schmax3[t];
    cs[1] = schsum3[t] * (1.f / 4096.f);
  }

  // y = relu(W1 @ [xh;xw] + b1)
  if (t < 128) {
    float in[16];
    #pragma unroll
    for (int i = 0; i < 16; i++) {
      float raw = (t < 64) ? s_rs[i * 64 + t] : s_xw[i * 64 + (t - 64)];
      in[i] = raw * (1.f / 64.f);
    }
    #pragma unroll
    for (int o = 0; o < 16; o++) {
      float acc = s_bb[o];
      #pragma unroll
      for (int i = 0; i < 16; i++) acc = fmaf(s_W[o * 16 + i], in[i], acc);
      s_y[o * 128 + t] = fmaxf(acc, 0.f);
    }
  }
  __syncthreads();
  // a_h = sigmoid(Wh @ y_h + bh), a_w = sigmoid(Ww @ y_w + bw) -> gmem
  if (t < 128) {
    const int hf = t >> 6, cc = t & 63;
    const float* Wm = s_W + 256 + hf * 256;
    const float* bm = s_bb + 16 + hf * 16;
    float in[16];
    #pragma unroll
    for (int i = 0; i < 16; i++) in[i] = s_y[i * 128 + t];
    float* gdst = hf ? (g_aw + g * 1024) : (g_ah + g * 1024);
    #pragma unroll
    for (int o = 0; o < 16; o++) {
      float acc = bm[o];
      #pragma unroll
      for (int i = 0; i < 16; i++) acc = fmaf(Wm[o * 16 + i], in[i], acc);
      gdst[o * 64 + cc] = 1.f / (1.f + __expf(-acc));
    }
  }
}

// ---------------------------------------------------------------------------
// KB: unchanged from the 149us configuration (512 thr, L2-resident passes).
__global__ void __launch_bounds__(512) kb_kernel(const float* __restrict__ x,
                                                 const float* __restrict__ gnw,
                                                 const float* __restrict__ gnb,
                                                 float* __restrict__ out)
{
  __shared__ float s_s[4096];
  __shared__ float s_ah[1024], s_aw[1024];
  __shared__ float s_k[16], s_e2[16], s_m3[16], s_w2[16], s_w3[16];
  __shared__ float schsum1[16], schsq1[16], schmax1[16], schmin1[16];
  __shared__ float s_r1[16];
  __shared__ float s_mu, s_rsd, s_smax, s_sinv;

  const int t = threadIdx.x, warp = t >> 5, lane = t & 31;
  const int g = blockIdx.x;
  const float* xg = x + (size_t)g * CG * HW;
  const __nv_bfloat16* x3g = g_x3 + (size_t)g * CG * HW;

  for (int i = t; i < 1024; i += 512) {
    s_ah[i] = g_ah[g * 1024 + i];
    s_aw[i] = g_aw[g * 1024 + i];
  }
  __syncthreads();

  // ---- pass 0: x1 statistics (warp == channel) ----
  {
    const int c = warp;
    const float* xc = xg + c * HW;
    const float* ahc = s_ah + c * 64;
    float aw0 = s_aw[c * 64 + lane * 2];
    float aw1 = s_aw[c * 64 + lane * 2 + 1];
    float sum = 0.f, sq = 0.f, mx = -1e30f, mn = 1e30f;
    #pragma unroll 4
    for (int m = 0; m < 64; m++) {
      float2 xv = *reinterpret_cast<const float2*>(xc + m * 64 + lane * 2);
      float a = ahc[m];
      float v0 = xv.x * a * aw0;
      float v1 = xv.y * a * aw1;
      sum += v0 + v1;
      sq += v0 * v0 + v1 * v1;
      mx = fmaxf(mx, fmaxf(v0, v1));
      mn = fminf(mn, fminf(v0, v1));
    }
    sum = wsum(sum); sq = wsum(sq); mx = wmax(mx); mn = wmin(mn);
    if (lane == 0) {
      schsum1[c] = sum; schsq1[c] = sq; schmax1[c] = mx; schmin1[c] = mn;
    }
  }
  __syncthreads();
  if (t == 0) {
    float a = 0.f, bq = 0.f;
    #pragma unroll
    for (int i = 0; i < 16; i++) { a += schsum1[i]; bq += schsq1[i]; }
    float mu = a * (1.f / 65536.f);
    float var = bq * (1.f / 65536.f) - mu * mu;
    s_mu = mu; s_rsd = rsqrtf(var + 1e-5f);
  }
  __syncthreads();
  if (t < 16) {
    int c = t;
    float k = s_rsd * gnw[c];
    float d = gnb[c] - s_mu * k;
    float mx1 = (k >= 0.f) ? schmax1[c] : schmin1[c];
    float max2 = mx1 * k + d;
    const float* cs = g_cs + (g * CG + c) * 2;
    s_k[c]  = k;
    s_e2[c] = d - max2;
    s_m3[c] = cs[0];                          // max3
    s_w2[c] = cs[1];                          // V3 (÷ Z2 in pass 1)
    s_w3[c] = schsum1[c] * (1.f / 4096.f) * k + d;  // V2 (÷ Z3 in pass 1)
  }
  __syncthreads();

  // ---- pass 1: per-channel Z2, Z3 (warp == channel, L2-hot reads) ----
  {
    const int c = warp;
    float k = s_k[c], e2 = s_e2[c], m3 = s_m3[c];
    const float* xc = xg + c * HW;
    const __nv_bfloat16* x3c = x3g + c * HW;
    const float* ahc = s_ah + c * 64;
    float aw0 = s_aw[c * 64 + lane * 2];
    float aw1 = s_aw[c * 64 + lane * 2 + 1];
    float z2 = 0.f, z3 = 0.f;
    #pragma unroll 4
    for (int m = 0; m < 64; m++) {
      float2 xv = *reinterpret_cast<const float2*>(xc + m * 64 + lane * 2);
      __nv_bfloat162 x3v = *reinterpret_cast<const __nv_bfloat162*>(x3c + m * 64 + lane * 2);
      float a = ahc[m];
      z2 += __expf(fmaf(xv.x * a * aw0, k, e2)) + __expf(fmaf(xv.y * a * aw1, k, e2));
      z3 += __expf(__bfloat162float(x3v.x) - m3) + __expf(__bfloat162float(x3v.y) - m3);
    }
    z2 = wsum(z2); z3 = wsum(z3);
    if (lane == 0) { s_w3[c] = s_w3[c] / z3; s_w2[c] = s_w2[c] / z2; }
  }
  __syncthreads();

  // ---- pass 2: s logits ----
  float lmax = -1e30f;
  #pragma unroll 1
  for (int rep = 0; rep < 8; rep++) {
    int l = t + rep * 512;
    int i = l >> 6, j = l & 63;
    float acc = 0.f;
    #pragma unroll
    for (int c = 0; c < 16; c++) {
      float x1 = xg[c * HW + l] * s_ah[c * 64 + i] * s_aw[c * 64 + j];
      acc += s_w2[c] * __expf(fmaf(x1, s_k[c], s_e2[c]));
      acc += s_w3[c] * __expf(__bfloat162float(x3g[c * HW + l]) - s_m3[c]);
    }
    s_s[l] = acc;
    lmax = fmaxf(lmax, acc);
  }
  lmax = wmax(lmax);
  if (lane == 0) s_r1[warp] = lmax;
  __syncthreads();
  if (t == 0) {
    float m = -1e30f;
    #pragma unroll
    for (int i = 0; i < 16; i++) m = fmaxf(m, s_r1[i]);
    s_smax = m;
  }
  __syncthreads();
  float lsum = 0.f;
  {
    float smax = s_smax;
    #pragma unroll 1
    for (int rep = 0; rep < 8; rep++) {
      int l = t + rep * 512;
      float e = __expf(s_s[l] - smax);
      s_s[l] = e;                           // store exp once
      lsum += e;
    }
  }
  lsum = wsum(lsum);
  if (lane == 0) s_r1[warp] = lsum;
  __syncthreads();
  if (t == 0) {
    float a = 0.f;
    #pragma unroll
    for (int i = 0; i < 16; i++) a += s_r1[i];
    s_sinv = 1.f / a;
  }
  __syncthreads();

  // ---- pass 3: out = x * (e * sinv) ----
  float* og = out + (size_t)g * CG * HW;
  float sinv = s_sinv;
  #pragma unroll 1
  for (int c = 0; c < 16; c++) {
    #pragma unroll
    for (int rep = 0; rep < 4; rep++) {
      int l0 = (t + rep * 512) * 2;
      float2 xv = *reinterpret_cast<const float2*>(xg + c * HW + l0);
      float2 ov;
      ov.x = xv.x * (s_s[l0] * sinv);
      ov.y = xv.y * (s_s[l0 + 1] * sinv);
      *reinterpret_cast<float2*>(og + c * HW + l0) = ov;
    }
  }
}

// ---------------------------------------------------------------------------
extern "C" void kernel_launch(void* const* d_in, const int* in_sizes, int n_in,
                              void* d_out, int out_size)
{
  const float* x   = (const float*)d_in[0];
  const float* w1  = (const float*)d_in[1];
  const float* b1  = (const float*)d_in[2];
  const float* wh  = (const float*)d_in[3];
  const float* bh  = (const float*)d_in[4];
  const float* ww  = (const float*)d_in[5];
  const float* bw  = (const float*)d_in[6];
  const float* w3  = (const float*)d_in[7];
  const float* b3  = (const float*)d_in[8];
  const float* gnw = (const float*)d_in[9];
  const float* gnb = (const float*)d_in[10];

  cudaFuncSetAttribute(ka_kernel, cudaFuncAttributeMaxDynamicSharedMemorySize,
                       SM_TOTF * (int)sizeof(float));
  ka_kernel<<<NG, 512, SM_TOTF * sizeof(float)>>>(x, w1, b1, wh, bh, ww, bw, w3, b3);
  kb_kernel<<<NG, 512>>>(x, gnw, gnb, (float*)d_out);
}